// round 11
// baseline (speedup 1.0000x reference)
#include <cuda_runtime.h>
#include <cstdint>

#define N_GROUPS 262144
#define EMBED_DIM 64

typedef unsigned long long u64;

struct ull4 { u64 x, y, z, w; };

__device__ __forceinline__ u64 mulx2(u64 a, u64 b) {
    u64 d; asm("mul.rn.f32x2 %0, %1, %2;" : "=l"(d) : "l"(a), "l"(b)); return d;
}
__device__ __forceinline__ u64 fmax2(u64 a, u64 b, u64 c) {
    u64 d; asm("fma.rn.f32x2 %0, %1, %2, %3;" : "=l"(d) : "l"(a), "l"(b), "l"(c)); return d;
}
__device__ __forceinline__ u64 pack2(float x, float y) {
    u64 d; asm("mov.b64 %0, {%1, %2};" : "=l"(d) : "f"(x), "f"(y)); return d;
}
__device__ __forceinline__ void unpack2(u64 a, float& x, float& y) {
    asm("mov.b64 {%0, %1}, %2;" : "=f"(x), "=f"(y) : "l"(a));
}
__device__ __forceinline__ float sigf(float x) {
    return __fdividef(1.0f, 1.0f + __expf(-x));
}
// 256-bit read-only gather with L2 evict-last retention (embed rows should
// out-compete their own stream in L2 so duplicate refs hit).
__device__ __forceinline__ ull4 ldg_el256(const float* p) {
    ull4 r;
    asm("ld.global.nc.L2::evict_last.v4.u64 {%0, %1, %2, %3}, [%4];"
        : "=l"(r.x), "=l"(r.y), "=l"(r.z), "=l"(r.w) : "l"(p));
    return r;
}
// Read-once index load: legacy .cs streaming hint (legal on b32) so the
// index stream never displaces embed rows in L2.
__device__ __forceinline__ int ldg_cs(const int* p) {
    int r;
    asm("ld.global.cs.b32 %0, [%1];" : "=r"(r) : "l"(p));
    return r;
}
// Streaming output store: keep the output out of L2's retained set.
__device__ __forceinline__ void stg_cs(float* p, float v) {
    asm volatile("st.global.cs.f32 [%0], %1;" :: "l"(p), "f"(v));
}

// 8 lanes per group, 4 groups per warp.
// Lane l3 covers dims [8*l3, 8*l3+8) via ONE 256-bit load per embedding row
// (8 lanes x 32B = fully coalesced 256B row, 3 LDG per group).
// W1 slices in padded smem (conflict-free LDS.128, 4-way broadcast).
__global__ __launch_bounds__(128, 7)
void afm_kernel(const int*   __restrict__ group,
                const float* __restrict__ embed,
                const float* __restrict__ W1,
                const float* __restrict__ b1,
                const float* __restrict__ W2,
                const float* __restrict__ b2,
                const float* __restrict__ Wp,
                const float* __restrict__ bp,
                float*       __restrict__ out)
{
    // smw[l3][dp*4+f] = (W1[8*l3+2*dp][f], W1[8*l3+2*dp+1][f]);
    // row stride 18 u64 = 144 B -> lane l3 hits banks 4*l3.. (conflict-free).
    __shared__ u64 smw[8][18];
    {
        const int t = threadIdx.x;           // blockDim.x == 128
        const int l   = t >> 4;
        const int idx = t & 15;
        const int dp = idx >> 2, f = idx & 3;
        const int d0 = 8 * l + 2 * dp;
        smw[l][dp * 4 + f] = pack2(W1[d0 * 4 + f], W1[(d0 + 1) * 4 + f]);
    }
    __syncthreads();

    const int lane = threadIdx.x & 31;
    const int sub  = lane >> 3;   // which of 4 groups in this warp
    const int l3   = lane & 7;    // lane within the 8-lane subgroup

    const int warp_global = (blockIdx.x * blockDim.x + threadIdx.x) >> 5;
    const int nwarps      = (gridDim.x * blockDim.x) >> 5;

    // Exchange leaves acc indices k0 = 2*bitrev3(l3), k1 = k0+1 on lane l3.
    const int br = ((l3 & 1) << 2) | (l3 & 2) | ((l3 & 4) >> 2);
    const int k0 = 2 * br, k1 = k0 + 1;
    const float b1a = (k0 < 12) ? b1[k0 & 3] : 0.0f;
    const float b1b = (k1 < 12) ? b1[k1 & 3] : 0.0f;
    const float w2a = (k0 < 12) ? W2[k0 & 3] : 0.0f;
    const float w2b = (k1 < 12) ? W2[k1 & 3] : 0.0f;
    // After the +4 pair-sum: a_0 on lanes {0,4}, a_1 on {2,6}, a_2 on {1,5}.
    const int q = l3 & 3;
    float mywp = 0.0f;
    if (q == 0) mywp = Wp[0];
    else if (q == 2) mywp = Wp[1];
    else if (q == 1) mywp = Wp[2];
    const float mybp = (q == 0) ? bp[0] : 0.0f;
    const float b2r  = b2[0];

    for (int g0 = warp_global * 8; g0 < N_GROUPS; g0 += nwarps * 8) {
        // One coalesced load of 24 indices = 8 groups (2 inner iterations).
        int v = 0;
        if (lane < 24) v = ldg_cs(group + g0 * 3 + lane);

#pragma unroll
        for (int it = 0; it < 2; it++) {
            const int g  = g0 + it * 4 + sub;
            const int i0 = __shfl_sync(0xffffffffu, v, it * 12 + sub * 3 + 0);
            const int i1 = __shfl_sync(0xffffffffu, v, it * 12 + sub * 3 + 1);
            const int i2 = __shfl_sync(0xffffffffu, v, it * 12 + sub * 3 + 2);

            const ull4 E0 = ldg_el256(embed + (size_t)i0 * EMBED_DIM + l3 * 8);
            const ull4 E1 = ldg_el256(embed + (size_t)i1 * EMBED_DIM + l3 * 8);
            const ull4 E2 = ldg_el256(embed + (size_t)i2 * EMBED_DIM + l3 * 8);

            u64 acc[12];
#pragma unroll
            for (int i = 0; i < 12; i++) acc[i] = 0ull;

#define DP(e0, e1, e2, dp)                                                  \
            {                                                               \
                const ulonglong2 wlo = *reinterpret_cast<const ulonglong2*>(\
                    &smw[l3][(dp) * 4 + 0]);                                \
                const ulonglong2 whi = *reinterpret_cast<const ulonglong2*>(\
                    &smw[l3][(dp) * 4 + 2]);                                \
                const u64 v01 = mulx2(e0, e1);                              \
                const u64 v02 = mulx2(e0, e2);                              \
                const u64 v12 = mulx2(e1, e2);                              \
                acc[0]  = fmax2(v01, wlo.x, acc[0]);                        \
                acc[1]  = fmax2(v01, wlo.y, acc[1]);                        \
                acc[2]  = fmax2(v01, whi.x, acc[2]);                        \
                acc[3]  = fmax2(v01, whi.y, acc[3]);                        \
                acc[4]  = fmax2(v02, wlo.x, acc[4]);                        \
                acc[5]  = fmax2(v02, wlo.y, acc[5]);                        \
                acc[6]  = fmax2(v02, whi.x, acc[6]);                        \
                acc[7]  = fmax2(v02, whi.y, acc[7]);                        \
                acc[8]  = fmax2(v12, wlo.x, acc[8]);                        \
                acc[9]  = fmax2(v12, wlo.y, acc[9]);                        \
                acc[10] = fmax2(v12, whi.x, acc[10]);                       \
                acc[11] = fmax2(v12, whi.y, acc[11]);                       \
            }
            DP(E0.x, E1.x, E2.x, 0)
            DP(E0.y, E1.y, E2.y, 1)
            DP(E0.z, E1.z, E2.z, 2)
            DP(E0.w, E1.w, E2.w, 3)
#undef DP

            // Fold packed halves -> 12 scalars (+4 zero pads).
            float r[16];
#pragma unroll
            for (int i = 0; i < 12; i++) {
                float x, y;
                unpack2(acc[i], x, y);
                r[i] = x + y;
            }
            r[12] = r[13] = r[14] = r[15] = 0.0f;

            // Exchange reduction over the 8-lane subgroup: 16 values,
            // 14 shuffles (masks 1, 2, 4). Serves all 4 groups at once.
            {
                const bool hb = l3 & 1;
#pragma unroll
                for (int j = 0; j < 8; j++) {
                    const float send = hb ? r[j] : r[j + 8];
                    const float recv = __shfl_xor_sync(0xffffffffu, send, 1);
                    r[j] = (hb ? r[j + 8] : r[j]) + recv;
                }
            }
            {
                const bool hb = l3 & 2;
#pragma unroll
                for (int j = 0; j < 4; j++) {
                    const float send = hb ? r[j] : r[j + 4];
                    const float recv = __shfl_xor_sync(0xffffffffu, send, 2);
                    r[j] = (hb ? r[j + 4] : r[j]) + recv;
                }
            }
            {
                const bool hb = l3 & 4;
#pragma unroll
                for (int j = 0; j < 2; j++) {
                    const float send = hb ? r[j] : r[j + 2];
                    const float recv = __shfl_xor_sync(0xffffffffu, send, 4);
                    r[j] = (hb ? r[j + 2] : r[j]) + recv;
                }
            }
            // Lane l3 now holds fully-reduced accs k0 = 2*bitrev3(l3), k0+1.

            // Distributed epilogue: two sigmoids per lane serve 4 groups.
            float t = sigf(r[0] + b1a) * w2a + sigf(r[1] + b1b) * w2b;
            t += __shfl_xor_sync(0xffffffffu, t, 4);
            float z = fmaf(t + b2r, mywp, mybp);
            z += __shfl_xor_sync(0xffffffffu, z, 1);
            z += __shfl_xor_sync(0xffffffffu, z, 2);

            if (l3 == 0)
                stg_cs(out + g, sigf(z) * 2.0f - 1.0f);
        }
    }
}

extern "C" void kernel_launch(void* const* d_in, const int* in_sizes, int n_in,
                              void* d_out, int out_size)
{
    const int*   group = (const int*)  d_in[0];
    const float* embed = (const float*)d_in[1];
    const float* W1    = (const float*)d_in[2];
    const float* b1    = (const float*)d_in[3];
    const float* W2    = (const float*)d_in[4];
    const float* b2    = (const float*)d_in[5];
    const float* Wp    = (const float*)d_in[6];
    const float* bp    = (const float*)d_in[7];
    float* out = (float*)d_out;

    const int blocks  = 1036;  // 148 SMs * 7 resident blocks of 128 threads
    const int threads = 128;
    afm_kernel<<<blocks, threads>>>(group, embed, W1, b1, W2, b2, Wp, bp, out);
}